// round 12
// baseline (speedup 1.0000x reference)
#include <cuda_runtime.h>
#include <cstdint>

#define N_NODES 200000
#define E_CAP   3200000
#define D 64

typedef unsigned long long u64;

// ---------------------------------------------------------------------------
// Scratch (allocation-free rule: __device__ globals; zero-initialized at load)
// ---------------------------------------------------------------------------
__device__ float g_h1 [(size_t)N_NODES * D];      // 51.2 MB intermediate
__device__ int   g_cnt   [N_NODES];               // ZERO at entry (invariant)
__device__ int   g_rowptr[N_NODES + 1];
__device__ int   g_cursor[N_NODES];
__device__ int2  g_cv    [E_CAP];                 // packed (col, val-bits)

// ---------------------------------------------------------------------------
// L2 residency policies
// ---------------------------------------------------------------------------
__device__ __forceinline__ u64 pol_keep() {
    u64 p; asm("createpolicy.fractional.L2::evict_last.b64 %0, 1.0;" : "=l"(p)); return p;
}
__device__ __forceinline__ u64 pol_stream() {
    u64 p; asm("createpolicy.fractional.L2::evict_first.b64 %0, 1.0;" : "=l"(p)); return p;
}
__device__ __forceinline__ float2 ld_f2_hint(const float2* p, u64 pol) {
    float2 v;
    asm volatile("ld.global.nc.L2::cache_hint.v2.f32 {%0,%1}, [%2], %3;"
                 : "=f"(v.x), "=f"(v.y) : "l"(p), "l"(pol));
    return v;
}
__device__ __forceinline__ int2 ld_i2_hint(const int2* p, u64 pol) {
    int2 v;
    asm volatile("ld.global.nc.L2::cache_hint.v2.b32 {%0,%1}, [%2], %3;"
                 : "=r"(v.x), "=r"(v.y) : "l"(p), "l"(pol));
    return v;
}
__device__ __forceinline__ void st_f4_hint(float4* p, float4 v, u64 pol) {
    asm volatile("st.global.L2::cache_hint.v4.f32 [%0], {%1,%2,%3,%4}, %5;"
                 :: "l"(p), "f"(v.x), "f"(v.y), "f"(v.z), "f"(v.w), "l"(pol) : "memory");
}
// Warp-uniform 16B W read (L1-resident; broadcast — no smem needed)
__device__ __forceinline__ ulonglong2 ldg_w2(const ulonglong2* p) {
    ulonglong2 v;
    asm("ld.global.nc.v2.u64 {%0,%1}, [%2];" : "=l"(v.x), "=l"(v.y) : "l"(p));
    return v;
}

// ---------------------------------------------------------------------------
// Packed fp32x2 helpers
// ---------------------------------------------------------------------------
__device__ __forceinline__ void fma2(u64& d, u64 a, u64 b) {
    asm("fma.rn.f32x2 %0, %1, %2, %0;" : "+l"(d) : "l"(a), "l"(b));
}
__device__ __forceinline__ u64 pk2(float lo, float hi) {
    u64 r; asm("mov.b64 %0, {%1, %2};" : "=l"(r) : "f"(lo), "f"(hi)); return r;
}
__device__ __forceinline__ u64 dup2(float x) {
    u64 r; asm("mov.b64 %0, {%1, %1};" : "=l"(r) : "f"(x)); return r;
}
__device__ __forceinline__ float2 upk2(u64 v) {
    float2 f; asm("mov.b64 {%0, %1}, %2;" : "=f"(f.x), "=f"(f.y) : "l"(v)); return f;
}

// ---------------------------------------------------------------------------
// CSR build (unchanged)
// ---------------------------------------------------------------------------
__global__ void zero_int_kernel(int* __restrict__ p, int n) {
    int i = blockIdx.x * blockDim.x + threadIdx.x;
    int stride = gridDim.x * blockDim.x;
    for (; i < n; i += stride) p[i] = 0;
}

__global__ void hist_kernel(const int* __restrict__ rows, int* __restrict__ cnt, int E) {
    int t = blockIdx.x * blockDim.x + threadIdx.x;
    int i0 = t * 4;
    if (i0 + 3 < E) {
        int r0 = __ldg(rows + i0),     r1 = __ldg(rows + i0 + 1);
        int r2 = __ldg(rows + i0 + 2), r3 = __ldg(rows + i0 + 3);
        atomicAdd(&cnt[r0], 1); atomicAdd(&cnt[r1], 1);
        atomicAdd(&cnt[r2], 1); atomicAdd(&cnt[r3], 1);
    } else {
        for (int i = i0; i < E; i++) atomicAdd(&cnt[__ldg(rows + i)], 1);
    }
}

__global__ void __launch_bounds__(1024)
scan_kernel(const int* __restrict__ cnt, int* __restrict__ rowptr,
            int* __restrict__ cursor, int n) {
    __shared__ int psum[1024];
    int tid = threadIdx.x;
    int per = (n + 1023) >> 10;
    int start = tid * per;
    int end   = start + per; if (end > n) end = n;
    if (start > n) start = n;

    int s = 0;
    for (int i = start; i < end; i++) s += cnt[i];
    psum[tid] = s;
    __syncthreads();
    for (int off = 1; off < 1024; off <<= 1) {
        int t = (tid >= off) ? psum[tid - off] : 0;
        __syncthreads();
        psum[tid] += t;
        __syncthreads();
    }
    int run = psum[tid] - s;
    for (int i = start; i < end; i++) {
        rowptr[i] = run;
        cursor[i] = run;
        run += cnt[i];
    }
    if (tid == 1023) rowptr[n] = psum[1023];
}

__global__ void scatter_kernel(const int*   __restrict__ rows,
                               const int*   __restrict__ cols,
                               const float* __restrict__ vals,
                               int*  __restrict__ cursor,
                               int2* __restrict__ cv, int E) {
    int t = blockIdx.x * blockDim.x + threadIdx.x;
    int i0 = t * 4;
    if (i0 + 3 < E) {
        int r0 = __ldg(rows + i0),     r1 = __ldg(rows + i0 + 1);
        int r2 = __ldg(rows + i0 + 2), r3 = __ldg(rows + i0 + 3);
        int c0 = __ldg(cols + i0),     c1 = __ldg(cols + i0 + 1);
        int c2 = __ldg(cols + i0 + 2), c3 = __ldg(cols + i0 + 3);
        float v0 = __ldg(vals + i0),     v1 = __ldg(vals + i0 + 1);
        float v2 = __ldg(vals + i0 + 2), v3 = __ldg(vals + i0 + 3);
        int p0 = atomicAdd(&cursor[r0], 1);
        int p1 = atomicAdd(&cursor[r1], 1);
        int p2 = atomicAdd(&cursor[r2], 1);
        int p3 = atomicAdd(&cursor[r3], 1);
        cv[p0] = make_int2(c0, __float_as_int(v0));
        cv[p1] = make_int2(c1, __float_as_int(v1));
        cv[p2] = make_int2(c2, __float_as_int(v2));
        cv[p3] = make_int2(c3, __float_as_int(v3));
    } else {
        for (int i = i0; i < E; i++) {
            int r   = __ldg(rows + i);
            int pos = atomicAdd(&cursor[r], 1);
            cv[pos] = make_int2(__ldg(cols + i), __float_as_int(__ldg(vals + i)));
        }
    }
}

// ---------------------------------------------------------------------------
// In-warp SpMM for one node (proven machinery)
// ---------------------------------------------------------------------------
__device__ __forceinline__ float2 spmm_row(const int*  __restrict__ rowptr,
                                           const int2* __restrict__ cv,
                                           const float2* __restrict__ x2,
                                           int node, int lane,
                                           u64 keep, u64 stream) {
    int s = __ldg(rowptr + node);
    int e = __ldg(rowptr + node + 1);

    float2 a0 = make_float2(0.f, 0.f), a1 = a0, a2 = a0, a3 = a0;

    for (int base = s; base < e; base += 32) {
        int m = e - base; if (m > 32) m = 32;          // m >= 1
        int idx = base + lane; if (idx >= e) idx = e - 1;
        int2 c = ld_i2_hint(cv + idx, stream);

        for (int j = 0; j < m; j += 4) {
            int   col[4];
            float val[4];
            #pragma unroll
            for (int k = 0; k < 4; k++) {
                int jk = j + k;
                int sl = jk < m ? jk : m - 1;          // clamp -> hot dup line
                col[k] = __shfl_sync(0xFFFFFFFFu, c.x, sl);
                float v = __int_as_float(__shfl_sync(0xFFFFFFFFu, c.y, sl));
                val[k] = (jk < m) ? v : 0.f;
            }
            float2 g[4];
            #pragma unroll
            for (int k = 0; k < 4; k++)
                g[k] = ld_f2_hint(x2 + (long long)col[k] * 32 + lane, keep);
            a0.x += val[0] * g[0].x;  a0.y += val[0] * g[0].y;
            a1.x += val[1] * g[1].x;  a1.y += val[1] * g[1].y;
            a2.x += val[2] * g[2].x;  a2.y += val[2] * g[2].y;
            a3.x += val[3] * g[3].x;  a3.y += val[3] * g[3].y;
        }
    }
    return make_float2((a0.x + a1.x) + (a2.x + a3.x),
                       (a0.y + a1.y) + (a2.y + a3.y));
}

// ---------------------------------------------------------------------------
// FUSED layer, broadcast-GEMM, high-occupancy version.
// 64 nodes/block, 256 threads, smem = combT ONLY (33.3 KB) -> 6 blocks/SM.
// Phase 1: warp w computes nbr for nodes w*8..w*8+7; stages comb TRANSPOSED.
// Phase 2: warp = 32 nodes (lane = node), fixed 16-col chunk per warp:
//          - W read: warp-uniform LDG.128 (L1-resident broadcast)
//          - activation read: combT[k][node] -> conflict-free LDS, 1 wf
// ---------------------------------------------------------------------------
#define NPB 64
#define TP  65

__global__ void __launch_bounds__(256, 6)
fused_layer_kernel(const int*  __restrict__ rowptr,
                   const int2* __restrict__ cv,
                   const float* __restrict__ x,    // [N][64] node features
                   const float* __restrict__ W,    // [128][64] row-major
                   const float* __restrict__ b,    // [64]
                   float*       __restrict__ out,  // [N][64]
                   int N, int keep_out) {
    __shared__ float combT[128 * TP];               // 33.3 KB

    int tid = threadIdx.x;
    int wid = tid >> 5, lane = tid & 31;
    int blockBase = blockIdx.x * NPB;

    u64 keep = pol_keep(), stream = pol_stream();
    const float2* x2 = (const float2*)x;

    // ---- Phase 1: SpMM + stage transposed comb ----
    #pragma unroll 2
    for (int r = 0; r < 8; r++) {
        int nl   = wid * 8 + r;              // node_local 0..63
        int node = blockBase + nl;
        if (node < N) {
            float2 nb = spmm_row(rowptr, cv, x2, node, lane, keep, stream);
            float2 hv = ld_f2_hint(x2 + (long long)node * 32 + lane, keep);
            combT[(2 * lane)      * TP + nl] = hv.x;
            combT[(2 * lane + 1)  * TP + nl] = hv.y;
            combT[(64 + 2 * lane) * TP + nl] = nb.x;
            combT[(65 + 2 * lane) * TP + nl] = nb.y;
        }
    }
    __syncthreads();

    // ---- Phase 2: GEMM + bias + ReLU ----
    int half = wid >> 2;                 // node half (0/1)
    int cw   = wid & 3;                  // column chunk: cols cw*16..cw*16+15
    int nl   = half * 32 + lane;         // this thread's node
    int node = blockBase + nl;
    if (node >= N) return;

    u64 acc[8];
    #pragma unroll
    for (int j = 0; j < 4; j++) {
        float4 bv = __ldg(((const float4*)b) + cw * 4 + j);
        acc[2 * j]     = pk2(bv.x, bv.y);
        acc[2 * j + 1] = pk2(bv.z, bv.w);
    }

    const float* cr = combT + nl;                              // + k*TP
    const ulonglong2* wk = ((const ulonglong2*)W) + cw * 4;    // + k*16

    #pragma unroll 4
    for (int k = 0; k < 128; k++) {
        u64 xv = dup2(cr[k * TP]);
        ulonglong2 w0 = ldg_w2(wk + k * 16 + 0);   // cols cw*16 + 0..3
        ulonglong2 w1 = ldg_w2(wk + k * 16 + 1);   // cols cw*16 + 4..7
        ulonglong2 w2 = ldg_w2(wk + k * 16 + 2);   // cols cw*16 + 8..11
        ulonglong2 w3 = ldg_w2(wk + k * 16 + 3);   // cols cw*16 + 12..15
        fma2(acc[0], xv, w0.x);  fma2(acc[1], xv, w0.y);
        fma2(acc[2], xv, w1.x);  fma2(acc[3], xv, w1.y);
        fma2(acc[4], xv, w2.x);  fma2(acc[5], xv, w2.y);
        fma2(acc[6], xv, w3.x);  fma2(acc[7], xv, w3.y);
    }

    u64 opol = keep_out ? keep : stream;
    float4* o4 = ((float4*)out) + (long long)node * 16 + cw * 4;
    #pragma unroll
    for (int j = 0; j < 4; j++) {
        float2 lo = upk2(acc[2 * j]), hi = upk2(acc[2 * j + 1]);
        float4 t;
        t.x = fmaxf(lo.x, 0.f); t.y = fmaxf(lo.y, 0.f);
        t.z = fmaxf(hi.x, 0.f); t.w = fmaxf(hi.y, 0.f);
        st_f4_hint(o4 + j, t, opol);
    }
}

// ---------------------------------------------------------------------------
// Launch order: hist(1) scan(2) scatter(3) fused1(4=ncu slot) fused2(5)
// zero_cnt(tail). g_cnt zero-at-entry invariant maintained.
// ---------------------------------------------------------------------------
extern "C" void kernel_launch(void* const* d_in, const int* in_sizes, int n_in,
                              void* d_out, int out_size) {
    const int*   rows = (const int*)  d_in[0];
    const int*   cols = (const int*)  d_in[1];
    const float* vals = (const float*)d_in[2];
    const float* emb  = (const float*)d_in[3];
    const float* W1   = (const float*)d_in[4];
    const float* b1   = (const float*)d_in[5];
    const float* W2   = (const float*)d_in[6];
    const float* b2   = (const float*)d_in[7];
    float* out = (float*)d_out;

    int E = in_sizes[0];
    int N = in_sizes[3] / D;

    float *h1;
    int *cnt, *rowptr, *cursor;
    int2 *cv;
    cudaGetSymbolAddress((void**)&h1,     g_h1);
    cudaGetSymbolAddress((void**)&cnt,    g_cnt);
    cudaGetSymbolAddress((void**)&rowptr, g_rowptr);
    cudaGetSymbolAddress((void**)&cursor, g_cursor);
    cudaGetSymbolAddress((void**)&cv,     g_cv);

    int eb4 = (E + 4 * 256 - 1) / (4 * 256);
    int fused_blocks = (N + NPB - 1) / NPB;

    // ---- CSR build (cnt pre-zeroed by invariant) ----
    hist_kernel   <<<eb4, 256>>>(rows, cnt, E);
    scan_kernel   <<<1, 1024>>>(cnt, rowptr, cursor, N);
    scatter_kernel<<<eb4, 256>>>(rows, cols, vals, cursor, cv, E);

    // ---- Layer 1 (fused spmm+concat+gemm+relu) ----
    fused_layer_kernel<<<fused_blocks, 256>>>(rowptr, cv, emb, W1, b1, h1, N, 1);

    // ---- Layer 2 ----
    fused_layer_kernel<<<fused_blocks, 256>>>(rowptr, cv, h1, W2, b2, out, N, 0);

    // ---- restore invariant ----
    zero_int_kernel<<<(N + 255) / 256, 256>>>(cnt, N);
}

// round 13
// speedup vs baseline: 1.2209x; 1.2209x over previous
#include <cuda_runtime.h>
#include <cstdint>

#define N_NODES 200000
#define E_CAP   3200000
#define D 64

typedef unsigned long long u64;

// ---------------------------------------------------------------------------
// Scratch (allocation-free rule: __device__ globals; zero-initialized at load)
// ---------------------------------------------------------------------------
__device__ float g_h1 [(size_t)N_NODES * D];      // 51.2 MB intermediate
__device__ int   g_cnt   [N_NODES];               // ZERO at entry (invariant)
__device__ int   g_rowptr[N_NODES + 1];
__device__ int   g_cursor[N_NODES];
__device__ int2  g_cv    [E_CAP];                 // packed (col, val-bits)

// ---------------------------------------------------------------------------
// L2 residency policies
// ---------------------------------------------------------------------------
__device__ __forceinline__ u64 pol_keep() {
    u64 p; asm("createpolicy.fractional.L2::evict_last.b64 %0, 1.0;" : "=l"(p)); return p;
}
__device__ __forceinline__ u64 pol_stream() {
    u64 p; asm("createpolicy.fractional.L2::evict_first.b64 %0, 1.0;" : "=l"(p)); return p;
}
__device__ __forceinline__ float2 ld_f2_hint(const float2* p, u64 pol) {
    float2 v;
    asm volatile("ld.global.nc.L2::cache_hint.v2.f32 {%0,%1}, [%2], %3;"
                 : "=f"(v.x), "=f"(v.y) : "l"(p), "l"(pol));
    return v;
}
__device__ __forceinline__ int2 ld_i2_hint(const int2* p, u64 pol) {
    int2 v;
    asm volatile("ld.global.nc.L2::cache_hint.v2.b32 {%0,%1}, [%2], %3;"
                 : "=r"(v.x), "=r"(v.y) : "l"(p), "l"(pol));
    return v;
}
__device__ __forceinline__ void st_f4_hint(float4* p, float4 v, u64 pol) {
    asm volatile("st.global.L2::cache_hint.v4.f32 [%0], {%1,%2,%3,%4}, %5;"
                 :: "l"(p), "f"(v.x), "f"(v.y), "f"(v.z), "f"(v.w), "l"(pol) : "memory");
}

// ---------------------------------------------------------------------------
// Packed fp32x2 helpers
// ---------------------------------------------------------------------------
__device__ __forceinline__ void fma2(u64& d, u64 a, u64 b) {
    asm("fma.rn.f32x2 %0, %1, %2, %0;" : "+l"(d) : "l"(a), "l"(b));
}
__device__ __forceinline__ u64 pk2(float lo, float hi) {
    u64 r; asm("mov.b64 %0, {%1, %2};" : "=l"(r) : "f"(lo), "f"(hi)); return r;
}
__device__ __forceinline__ u64 dup2(float x) {
    u64 r; asm("mov.b64 %0, {%1, %1};" : "=l"(r) : "f"(x)); return r;
}
__device__ __forceinline__ float2 upk2(u64 v) {
    float2 f; asm("mov.b64 {%0, %1}, %2;" : "=f"(f.x), "=f"(f.y) : "l"(v)); return f;
}

// ---------------------------------------------------------------------------
// CSR build (unchanged)
// ---------------------------------------------------------------------------
__global__ void zero_int_kernel(int* __restrict__ p, int n) {
    int i = blockIdx.x * blockDim.x + threadIdx.x;
    int stride = gridDim.x * blockDim.x;
    for (; i < n; i += stride) p[i] = 0;
}

__global__ void hist_kernel(const int* __restrict__ rows, int* __restrict__ cnt, int E) {
    int t = blockIdx.x * blockDim.x + threadIdx.x;
    int i0 = t * 4;
    if (i0 + 3 < E) {
        int r0 = __ldg(rows + i0),     r1 = __ldg(rows + i0 + 1);
        int r2 = __ldg(rows + i0 + 2), r3 = __ldg(rows + i0 + 3);
        atomicAdd(&cnt[r0], 1); atomicAdd(&cnt[r1], 1);
        atomicAdd(&cnt[r2], 1); atomicAdd(&cnt[r3], 1);
    } else {
        for (int i = i0; i < E; i++) atomicAdd(&cnt[__ldg(rows + i)], 1);
    }
}

__global__ void __launch_bounds__(1024)
scan_kernel(const int* __restrict__ cnt, int* __restrict__ rowptr,
            int* __restrict__ cursor, int n) {
    __shared__ int psum[1024];
    int tid = threadIdx.x;
    int per = (n + 1023) >> 10;
    int start = tid * per;
    int end   = start + per; if (end > n) end = n;
    if (start > n) start = n;

    int s = 0;
    for (int i = start; i < end; i++) s += cnt[i];
    psum[tid] = s;
    __syncthreads();
    for (int off = 1; off < 1024; off <<= 1) {
        int t = (tid >= off) ? psum[tid - off] : 0;
        __syncthreads();
        psum[tid] += t;
        __syncthreads();
    }
    int run = psum[tid] - s;
    for (int i = start; i < end; i++) {
        rowptr[i] = run;
        cursor[i] = run;
        run += cnt[i];
    }
    if (tid == 1023) rowptr[n] = psum[1023];
}

__global__ void scatter_kernel(const int*   __restrict__ rows,
                               const int*   __restrict__ cols,
                               const float* __restrict__ vals,
                               int*  __restrict__ cursor,
                               int2* __restrict__ cv, int E) {
    int t = blockIdx.x * blockDim.x + threadIdx.x;
    int i0 = t * 4;
    if (i0 + 3 < E) {
        int r0 = __ldg(rows + i0),     r1 = __ldg(rows + i0 + 1);
        int r2 = __ldg(rows + i0 + 2), r3 = __ldg(rows + i0 + 3);
        int c0 = __ldg(cols + i0),     c1 = __ldg(cols + i0 + 1);
        int c2 = __ldg(cols + i0 + 2), c3 = __ldg(cols + i0 + 3);
        float v0 = __ldg(vals + i0),     v1 = __ldg(vals + i0 + 1);
        float v2 = __ldg(vals + i0 + 2), v3 = __ldg(vals + i0 + 3);
        int p0 = atomicAdd(&cursor[r0], 1);
        int p1 = atomicAdd(&cursor[r1], 1);
        int p2 = atomicAdd(&cursor[r2], 1);
        int p3 = atomicAdd(&cursor[r3], 1);
        cv[p0] = make_int2(c0, __float_as_int(v0));
        cv[p1] = make_int2(c1, __float_as_int(v1));
        cv[p2] = make_int2(c2, __float_as_int(v2));
        cv[p3] = make_int2(c3, __float_as_int(v3));
    } else {
        for (int i = i0; i < E; i++) {
            int r   = __ldg(rows + i);
            int pos = atomicAdd(&cursor[r], 1);
            cv[pos] = make_int2(__ldg(cols + i), __float_as_int(__ldg(vals + i)));
        }
    }
}

// ---------------------------------------------------------------------------
// Interleaved PAIR SpMM: two nodes at once. Per while-iteration: 2 independent
// metadata LDGs, then batches issuing 4+4 independent gathers before FMAs.
// Warp-uniform control; clamp+zero predication (no scalar tails).
// ---------------------------------------------------------------------------
__device__ __forceinline__ void spmm_pair(int sA, int eA, int sB, int eB,
                                          const int2* __restrict__ cv,
                                          const float2* __restrict__ x2,
                                          int lane, u64 keep, u64 stream,
                                          float2& outA, float2& outB) {
    float2 aA0 = make_float2(0.f, 0.f), aA1 = aA0;
    float2 aB0 = aA0, aB1 = aA0;
    int baseA = sA, baseB = sB;

    while (baseA < eA || baseB < eB) {
        int mA = 0, mB = 0;
        int2 cA, cB;
        if (baseA < eA) {
            mA = eA - baseA; if (mA > 32) mA = 32;
            int idx = baseA + lane; if (idx >= eA) idx = eA - 1;
            cA = ld_i2_hint(cv + idx, stream);
        }
        if (baseB < eB) {
            mB = eB - baseB; if (mB > 32) mB = 32;
            int idx = baseB + lane; if (idx >= eB) idx = eB - 1;
            cB = ld_i2_hint(cv + idx, stream);
        }
        int mm = mA > mB ? mA : mB;

        for (int j = 0; j < mm; j += 4) {
            bool dA = j < mA, dB = j < mB;        // warp-uniform
            float vA[4], vB[4];
            float2 gA[4], gB[4];
            if (dA) {
                #pragma unroll
                for (int k = 0; k < 4; k++) {
                    int jk = j + k;
                    int sl = jk < mA ? jk : mA - 1;
                    int col = __shfl_sync(0xFFFFFFFFu, cA.x, sl);
                    float v = __int_as_float(__shfl_sync(0xFFFFFFFFu, cA.y, sl));
                    vA[k] = (jk < mA) ? v : 0.f;
                    gA[k] = ld_f2_hint(x2 + (long long)col * 32 + lane, keep);
                }
            }
            if (dB) {
                #pragma unroll
                for (int k = 0; k < 4; k++) {
                    int jk = j + k;
                    int sl = jk < mB ? jk : mB - 1;
                    int col = __shfl_sync(0xFFFFFFFFu, cB.x, sl);
                    float v = __int_as_float(__shfl_sync(0xFFFFFFFFu, cB.y, sl));
                    vB[k] = (jk < mB) ? v : 0.f;
                    gB[k] = ld_f2_hint(x2 + (long long)col * 32 + lane, keep);
                }
            }
            if (dA) {
                aA0.x += vA[0] * gA[0].x;  aA0.y += vA[0] * gA[0].y;
                aA1.x += vA[1] * gA[1].x;  aA1.y += vA[1] * gA[1].y;
                aA0.x += vA[2] * gA[2].x;  aA0.y += vA[2] * gA[2].y;
                aA1.x += vA[3] * gA[3].x;  aA1.y += vA[3] * gA[3].y;
            }
            if (dB) {
                aB0.x += vB[0] * gB[0].x;  aB0.y += vB[0] * gB[0].y;
                aB1.x += vB[1] * gB[1].x;  aB1.y += vB[1] * gB[1].y;
                aB0.x += vB[2] * gB[2].x;  aB0.y += vB[2] * gB[2].y;
                aB1.x += vB[3] * gB[3].x;  aB1.y += vB[3] * gB[3].y;
            }
        }
        baseA += 32;
        baseB += 32;
    }
    outA = make_float2(aA0.x + aA1.x, aA0.y + aA1.y);
    outB = make_float2(aB0.x + aB1.x, aB0.y + aB1.y);
}

// ---------------------------------------------------------------------------
// FUSED layer. 64 nodes/block, 256 threads, dynamic smem 66 KB:
//   Ws 32 KB (W broadcast source) + combT [128][65] 33.3 KB.
// Phase 1: warp = 8 nodes as 4 interleaved pairs; rowptr prefetched (9 LDGs).
// Phase 2: warp = 32 nodes (lane = node), 16-col chunk per warp:
//   W = LDS.128 warp-uniform broadcast, activations = conflict-free LDS.
// ---------------------------------------------------------------------------
#define NPB 64
#define TP  65
#define FUSED_SMEM ((128*64 + 128*TP) * sizeof(float))   // 66048 B

__global__ void __launch_bounds__(256)
fused_layer_kernel(const int*  __restrict__ rowptr,
                   const int2* __restrict__ cv,
                   const float* __restrict__ x,    // [N][64] node features
                   const float* __restrict__ W,    // [128][64] row-major
                   const float* __restrict__ b,    // [64]
                   float*       __restrict__ out,  // [N][64]
                   int N, int keep_out) {
    extern __shared__ float smem[];
    float* Ws    = smem;            // 128*64
    float* combT = smem + 128 * 64; // [128][TP]

    int tid = threadIdx.x;
    const float4* Wg  = (const float4*)W;
    float4*       Ws4 = (float4*)Ws;
    #pragma unroll
    for (int i = 0; i < 8; i++) Ws4[tid + i * 256] = __ldg(Wg + tid + i * 256);

    int wid = tid >> 5, lane = tid & 31;
    int blockBase = blockIdx.x * NPB;

    u64 keep = pol_keep(), stream = pol_stream();
    const float2* x2 = (const float2*)x;

    // ---- Phase 1: prefetch rowptr, then 4 interleaved node-pairs ----
    int nbase = blockBase + wid * 8;
    int rp_l = 0;
    if (lane < 9) {
        int idx = nbase + lane; if (idx > N) idx = N;
        rp_l = __ldg(rowptr + idx);
    }

    #pragma unroll
    for (int pr = 0; pr < 4; pr++) {
        int r0 = 2 * pr;
        int sA = __shfl_sync(0xFFFFFFFFu, rp_l, r0);
        int eA = __shfl_sync(0xFFFFFFFFu, rp_l, r0 + 1);
        int eB = __shfl_sync(0xFFFFFFFFu, rp_l, r0 + 2);
        int sB = eA;                      // rows are contiguous in CSR

        float2 A, B;
        spmm_pair(sA, eA, sB, eB, cv, x2, lane, keep, stream, A, B);

        int nA = nbase + r0, nB = nbase + r0 + 1;
        int nlA = wid * 8 + r0, nlB = nlA + 1;
        if (nA < N) {
            float2 hv = ld_f2_hint(x2 + (long long)nA * 32 + lane, keep);
            combT[(2 * lane)      * TP + nlA] = hv.x;
            combT[(2 * lane + 1)  * TP + nlA] = hv.y;
            combT[(64 + 2 * lane) * TP + nlA] = A.x;
            combT[(65 + 2 * lane) * TP + nlA] = A.y;
        }
        if (nB < N) {
            float2 hv = ld_f2_hint(x2 + (long long)nB * 32 + lane, keep);
            combT[(2 * lane)      * TP + nlB] = hv.x;
            combT[(2 * lane + 1)  * TP + nlB] = hv.y;
            combT[(64 + 2 * lane) * TP + nlB] = B.x;
            combT[(65 + 2 * lane) * TP + nlB] = B.y;
        }
    }
    __syncthreads();

    // ---- Phase 2: GEMM + bias + ReLU (R11 broadcast form) ----
    int half = wid >> 2;                 // node half (0/1)
    int cw   = wid & 3;                  // column chunk: cols cw*16..cw*16+15
    int nl   = half * 32 + lane;         // this thread's node
    int node = blockBase + nl;
    if (node >= N) return;

    u64 acc[8];
    #pragma unroll
    for (int j = 0; j < 4; j++) {
        float4 bv = __ldg(((const float4*)b) + cw * 4 + j);
        acc[2 * j]     = pk2(bv.x, bv.y);
        acc[2 * j + 1] = pk2(bv.z, bv.w);
    }

    const float* cr = combT + nl;                              // + k*TP
    const ulonglong2* wk = ((const ulonglong2*)Ws) + cw * 4;   // + k*16

    #pragma unroll 4
    for (int k = 0; k < 128; k++) {
        u64 xv = dup2(cr[k * TP]);
        ulonglong2 w0 = wk[k * 16 + 0];
        ulonglong2 w1 = wk[k * 16 + 1];
        ulonglong2 w2 = wk[k * 16 + 2];
        ulonglong2 w3 = wk[k * 16 + 3];
        fma2(acc[0], xv, w0.x);  fma2(acc[1], xv, w0.y);
        fma2(acc[2], xv, w1.x);  fma2(acc[3], xv, w1.y);
        fma2(acc[4], xv, w2.x);  fma2(acc[5], xv, w2.y);
        fma2(acc[6], xv, w3.x);  fma2(acc[7], xv, w3.y);
    }

    u64 opol = keep_out ? keep : stream;
    float4* o4 = ((float4*)out) + (long long)node * 16 + cw * 4;
    #pragma unroll
    for (int j = 0; j < 4; j++) {
        float2 lo = upk2(acc[2 * j]), hi = upk2(acc[2 * j + 1]);
        float4 t;
        t.x = fmaxf(lo.x, 0.f); t.y = fmaxf(lo.y, 0.f);
        t.z = fmaxf(hi.x, 0.f); t.w = fmaxf(hi.y, 0.f);
        st_f4_hint(o4 + j, t, opol);
    }
}

// ---------------------------------------------------------------------------
// Launch order: hist(1) scan(2) scatter(3) fused1(4=ncu slot) fused2(5)
// zero_cnt(tail). g_cnt zero-at-entry invariant maintained.
// ---------------------------------------------------------------------------
extern "C" void kernel_launch(void* const* d_in, const int* in_sizes, int n_in,
                              void* d_out, int out_size) {
    const int*   rows = (const int*)  d_in[0];
    const int*   cols = (const int*)  d_in[1];
    const float* vals = (const float*)d_in[2];
    const float* emb  = (const float*)d_in[3];
    const float* W1   = (const float*)d_in[4];
    const float* b1   = (const float*)d_in[5];
    const float* W2   = (const float*)d_in[6];
    const float* b2   = (const float*)d_in[7];
    float* out = (float*)d_out;

    int E = in_sizes[0];
    int N = in_sizes[3] / D;

    float *h1;
    int *cnt, *rowptr, *cursor;
    int2 *cv;
    cudaGetSymbolAddress((void**)&h1,     g_h1);
    cudaGetSymbolAddress((void**)&cnt,    g_cnt);
    cudaGetSymbolAddress((void**)&rowptr, g_rowptr);
    cudaGetSymbolAddress((void**)&cursor, g_cursor);
    cudaGetSymbolAddress((void**)&cv,     g_cv);

    cudaFuncSetAttribute(fused_layer_kernel,
                         cudaFuncAttributeMaxDynamicSharedMemorySize,
                         (int)FUSED_SMEM);

    int eb4 = (E + 4 * 256 - 1) / (4 * 256);
    int fused_blocks = (N + NPB - 1) / NPB;

    // ---- CSR build (cnt pre-zeroed by invariant) ----
    hist_kernel   <<<eb4, 256>>>(rows, cnt, E);
    scan_kernel   <<<1, 1024>>>(cnt, rowptr, cursor, N);
    scatter_kernel<<<eb4, 256>>>(rows, cols, vals, cursor, cv, E);

    // ---- Layer 1 (fused spmm+concat+gemm+relu) ----
    fused_layer_kernel<<<fused_blocks, 256, FUSED_SMEM>>>(rowptr, cv, emb, W1, b1, h1, N, 1);

    // ---- Layer 2 ----
    fused_layer_kernel<<<fused_blocks, 256, FUSED_SMEM>>>(rowptr, cv, h1, W2, b2, out, N, 0);

    // ---- restore invariant ----
    zero_int_kernel<<<(N + 255) / 256, 256>>>(cnt, N);
}